// round 6
// baseline (speedup 1.0000x reference)
#include <cuda_runtime.h>

#define NB 1024
#define LD 32
#define HD 64
#define TJ 128
#define NT 256
#define EPSV 1e-6f
#define SELF_SCALE 0.5f
#define INT_SCALE 0.3f

// Scratch (device globals; no allocation allowed in kernel_launch)
__device__ __align__(16) float g_A[NB * HD];      // a_i            [i][k]
__device__ __align__(16) float g_BvT[HD * NB];    // b_j transposed [k][j]
__device__ __align__(16) float g_CI[NB * LD];     // h @ Wc[:, :L].T
__device__ __align__(16) float g_CJ[NB * LD];     // h @ Wc[:, L:].T
__device__ __align__(16) float g_SELF[NB * LD];   // self_term
__device__ __align__(16) float g_Hh[NB * LD];     // packed h rows
__device__ float g_AG[NB];                        // sigmoid(aggr)
__device__ float g_PH[NB];                        // phases

__device__ __forceinline__ float tanh_fast(float x) {
    // 1 - 2/(exp(2x)+1): exact at saturation, ~1e-7 rel err
    float e = __expf(2.0f * x);
    return 1.0f - __fdividef(2.0f, e + 1.0f);
}

// ---------------------------------------------------------------------------
// Phase 1: per-node precompute. One block (64 threads) per node i.
// ---------------------------------------------------------------------------
__global__ void phase1_kernel(
    const float* __restrict__ state,
    const float* __restrict__ Ws1, const float* __restrict__ bs1,
    const float* __restrict__ Ws2, const float* __restrict__ bs2,
    const float* __restrict__ Ws3, const float* __restrict__ bs3,
    const float* __restrict__ Wi1, const float* __restrict__ bi1,
    const float* __restrict__ Wc,  const float* __restrict__ aggr)
{
    int i = blockIdx.x;
    int t = threadIdx.x;  // 0..63

    __shared__ float sh[LD], st1[HD], st2[HD], sdh[LD];

    if (t < LD) sh[t] = state[i * (LD + 1) + t];
    __syncthreads();

    float acc = bs1[t];
#pragma unroll
    for (int l = 0; l < LD; l++) acc += Ws1[t * LD + l] * sh[l];
    st1[t] = tanhf(acc);
    __syncthreads();

    acc = bs2[t];
#pragma unroll
    for (int k = 0; k < HD; k++) acc += Ws2[t * HD + k] * st1[k];
    st2[t] = tanhf(acc);
    __syncthreads();

    if (t < LD) {
        acc = bs3[t];
#pragma unroll
        for (int k = 0; k < HD; k++) acc += Ws3[t * HD + k] * st2[k];
        sdh[t] = acc;
        g_SELF[i * LD + t] = acc;
        g_Hh[i * LD + t] = sh[t];
    }
    __syncthreads();

    // a_i = h@Wi1[:, :L].T + dh@Wi1[:, 2L:3L].T
    // b_i = h@Wi1[:, L:2L].T + dh@Wi1[:, 3L:].T + bi1
    float a = 0.0f, b = bi1[t];
#pragma unroll
    for (int l = 0; l < LD; l++) {
        float hv = sh[l], dv = sdh[l];
        const float* row = Wi1 + t * (4 * LD);
        a += row[l] * hv + row[2 * LD + l] * dv;
        b += row[LD + l] * hv + row[3 * LD + l] * dv;
    }
    g_A[i * HD + t] = a;
    g_BvT[t * NB + i] = b;   // transposed for coalesced phase-2 reads

    if (t < LD) {
        float ci = 0.0f, cj = 0.0f;
#pragma unroll
        for (int m = 0; m < LD; m++) {
            ci += Wc[t * (2 * LD) + m] * sh[m];
            cj += Wc[t * (2 * LD) + LD + m] * sh[m];
        }
        g_CI[i * LD + t] = ci;
        g_CJ[i * LD + t] = cj;
    }
    if (t == 0) {
        g_AG[i] = 1.0f / (1.0f + expf(-aggr[i]));
        g_PH[i] = state[i * (LD + 1) + LD];
    }
}

// ---------------------------------------------------------------------------
// Phase 2: one block (256 threads) per i; j tiled by 128.
//   stage 1 : x1T[k][j] in SMEM + per-j scale s_j + quantum term
//   stage 2 : register-tiled GEMM y = x1 @ Wi2^T, tanh, fold into colsum[r]
//   finish  : isum_l = colsum @ Wi3[l,:] + ssum*bi3[l] + qsum[l]
// ---------------------------------------------------------------------------
__global__ void __launch_bounds__(NT) phase2_kernel(
    const float* __restrict__ Wi2, const float* __restrict__ bi2,
    const float* __restrict__ Wi3, const float* __restrict__ bi3,
    const float* __restrict__ phase_w, const float* __restrict__ bc,
    float* __restrict__ out)
{
    __shared__ __align__(16) float sWi2T[HD * HD];   // [k][r]  16 KB
    __shared__ __align__(16) float sX1T[HD][TJ];     // [k][j]  32 KB
    __shared__ float sS[TJ];
    __shared__ float sA[HD], sBi2[HD];
    __shared__ float sHi[LD], sCi[LD], sPw[LD], sBc[LD];
    __shared__ float sColRed[16][HD];                // 4 KB
    __shared__ float sQRed[8][LD];
    __shared__ float sSsumRed[8];
    __shared__ float sColsum[HD];
    __shared__ float sSsum;

    int i = blockIdx.x;
    int tid = threadIdx.x;
    int lane = tid & 31;
    int warp = tid >> 5;

    for (int idx = tid; idx < HD * HD; idx += NT) {
        int k = idx >> 6, r = idx & 63;
        sWi2T[idx] = Wi2[r * HD + k];          // sWi2T[k][r]
    }
    if (tid < HD) { sA[tid] = g_A[i * HD + tid]; sBi2[tid] = bi2[tid]; }
    if (tid < LD) {
        sHi[tid] = g_Hh[i * LD + tid];
        sCi[tid] = g_CI[i * LD + tid];
        sPw[tid] = phase_w[tid];
        sBc[tid] = bc[tid];
    }
    __syncthreads();

    float agg_i = g_AG[i];
    float ph_i  = g_PH[i];
    float hi_l = sHi[lane], ci_l = sCi[lane], pw_l = sPw[lane], bc_l = sBc[lane];

    float colsum0 = 0.f, colsum1 = 0.f, colsum2 = 0.f, colsum3 = 0.f;
    float qacc = 0.f;
    float ssum = 0.f;

    int jj1 = tid & 127;           // stage-1 j index
    int kh  = (tid >> 7) * 32;     // stage-1 k half
    int jt = tid & 15, rt = tid >> 4;
    int jb = jt * 8, rb = rt * 4;

    for (int t = 0; t < 8; t++) {
        int j0 = t * TJ;

        // ---- stage 1a: x1T[k][j] = tanh(a_i[k] + b_j[k]) ----
#pragma unroll
        for (int u = 0; u < 32; u++) {
            float b = g_BvT[(kh + u) * NB + j0 + jj1];   // coalesced
            sX1T[kh + u][jj1] = tanh_fast(sA[kh + u] + b);
        }

        // ---- stage 1b: dist + quantum. One warp per 16 j, lane = l ----
#pragma unroll 1
        for (int v = 0; v < 16; v++) {
            int j = j0 + warp * 16 + v;
            float hj = g_Hh[j * LD + lane];              // coalesced
            float e = hj - hi_l;
            float d2 = e * e;
#pragma unroll
            for (int o = 16; o > 0; o >>= 1)
                d2 += __shfl_xor_sync(0xffffffffu, d2, o);
            float s = fminf(__fdividef(1.0f, sqrtf(d2) + EPSV), 2.0f) * agg_i;
            if (j == i) s = 0.0f;
            if (lane == 0) { sS[warp * 16 + v] = s; ssum += s; }

            float pd = ph_i - g_PH[j];
            float cj = g_CJ[j * LD + lane];              // coalesced
            float pf = __cosf(pd * pw_l);
            float z  = ci_l + cj + bc_l;
            float coh = __fdividef(1.0f, 1.0f + __expf(-z));
            qacc += pf * coh * e;                        // pf*coh*(hj - hi)
        }
        __syncthreads();

        // ---- stage 2: GEMM micro-tile 8j x 4r per thread ----
        float acc[8][4];
#pragma unroll
        for (int u = 0; u < 8; u++)
#pragma unroll
            for (int v = 0; v < 4; v++) acc[u][v] = 0.0f;

#pragma unroll 8
        for (int k = 0; k < HD; k++) {
            float4 xa = *(const float4*)&sX1T[k][jb];
            float4 xb = *(const float4*)&sX1T[k][jb + 4];
            float4 w  = *(const float4*)&sWi2T[k * HD + rb];
            float xv[8] = {xa.x, xa.y, xa.z, xa.w, xb.x, xb.y, xb.z, xb.w};
            float wv[4] = {w.x, w.y, w.z, w.w};
#pragma unroll
            for (int u = 0; u < 8; u++)
#pragma unroll
                for (int v = 0; v < 4; v++)
                    acc[u][v] += xv[u] * wv[v];
        }

        // epilogue: x2 = tanh(acc + bi2), weight by s_j, fold into colsum[r]
        float b0 = sBi2[rb], b1 = sBi2[rb + 1], b2 = sBi2[rb + 2], b3 = sBi2[rb + 3];
#pragma unroll
        for (int u = 0; u < 8; u++) {
            float su = sS[jb + u];
            colsum0 += su * tanh_fast(acc[u][0] + b0);
            colsum1 += su * tanh_fast(acc[u][1] + b1);
            colsum2 += su * tanh_fast(acc[u][2] + b2);
            colsum3 += su * tanh_fast(acc[u][3] + b3);
        }
        __syncthreads();   // protect sX1T/sS before next tile overwrites
    }

    // ---- reductions ----
    sColRed[jt][rb + 0] = colsum0;
    sColRed[jt][rb + 1] = colsum1;
    sColRed[jt][rb + 2] = colsum2;
    sColRed[jt][rb + 3] = colsum3;
    sQRed[warp][lane] = qacc;                 // lane = l (32 wide)
    if (lane == 0) sSsumRed[warp] = ssum;
    __syncthreads();

    if (tid < HD) {
        float c = 0.0f;
#pragma unroll
        for (int u = 0; u < 16; u++) c += sColRed[u][tid];
        sColsum[tid] = c;
    }
    if (tid == 0) {
        float sst = 0.0f;
#pragma unroll
        for (int u = 0; u < 8; u++) sst += sSsumRed[u];
        sSsum = sst;
    }
    __syncthreads();

    if (tid < LD) {
        float q = 0.0f;
#pragma unroll
        for (int u = 0; u < 8; u++) q += sQRed[u][tid];
        float kv = sSsum * bi3[tid];
#pragma unroll
        for (int r = 0; r < HD; r++) kv += sColsum[r] * Wi3[tid * HD + r];
        float v = kv + q;                               // isum[l]
        out[i * (LD + 1) + tid] = SELF_SCALE * g_SELF[i * LD + tid] + INT_SCALE * v;
        float av = fabsf(v);
#pragma unroll
        for (int o = 16; o > 0; o >>= 1)
            av += __shfl_down_sync(0xffffffffu, av, o);
        if (tid == 0)
            out[i * (LD + 1) + LD] = 0.1f + 0.05f * av;
    }
}

// ---------------------------------------------------------------------------
extern "C" void kernel_launch(void* const* d_in, const int* in_sizes, int n_in,
                              void* d_out, int out_size)
{
    const float* state   = (const float*)d_in[0];
    const float* Ws1     = (const float*)d_in[1];
    const float* bs1     = (const float*)d_in[2];
    const float* Ws2     = (const float*)d_in[3];
    const float* bs2     = (const float*)d_in[4];
    const float* Ws3     = (const float*)d_in[5];
    const float* bs3     = (const float*)d_in[6];
    const float* Wi1     = (const float*)d_in[7];
    const float* bi1     = (const float*)d_in[8];
    const float* Wi2     = (const float*)d_in[9];
    const float* bi2     = (const float*)d_in[10];
    const float* Wi3     = (const float*)d_in[11];
    const float* bi3     = (const float*)d_in[12];
    const float* phase_w = (const float*)d_in[13];
    const float* Wc      = (const float*)d_in[14];
    const float* bc      = (const float*)d_in[15];
    const float* aggr    = (const float*)d_in[16];
    float* out = (float*)d_out;

    phase1_kernel<<<NB, 64>>>(state, Ws1, bs1, Ws2, bs2, Ws3, bs3,
                              Wi1, bi1, Wc, aggr);
    phase2_kernel<<<NB, NT>>>(Wi2, bi2, Wi3, bi3, phase_w, bc, out);
}

// round 11
// speedup vs baseline: 1.3310x; 1.3310x over previous
#include <cuda_runtime.h>
#include <cuda_bf16.h>
#include <cstdint>

#define NB 1024
#define LD 32
#define HD 64
#define NT 256
#define EPSV 1e-6f
#define SELF_SCALE 0.5f
#define INT_SCALE 0.3f

// ---------------- device scratch ----------------
__device__ __align__(16) float g_A[NB * HD];     // a_i   [i][k]
__device__ __align__(16) float g_Bv[NB * HD];    // b_j   [j][k]
__device__ __align__(16) float g_CI[NB * LD];
__device__ __align__(16) float g_CJ[NB * LD];
__device__ __align__(16) float g_SELF[NB * LD];
__device__ __align__(16) float g_Hh[NB * LD];
__device__ float g_AG[NB];
__device__ float g_PH[NB];

__device__ __forceinline__ float tanh_fast(float x) {
    float e = __expf(2.0f * x);
    return 1.0f - __fdividef(2.0f, e + 1.0f);
}

__device__ __forceinline__ uint32_t smem_u32(const void* p) {
    uint32_t a;
    asm("{ .reg .u64 t; cvta.to.shared.u64 t, %1; cvt.u32.u64 %0, t; }" : "=r"(a) : "l"(p));
    return a;
}

#define LDM4(r0, r1, r2, r3, addr)                                          \
    asm volatile("ldmatrix.sync.aligned.m8n8.x4.shared.b16 {%0,%1,%2,%3}, [%4];" \
        : "=r"(r0), "=r"(r1), "=r"(r2), "=r"(r3) : "r"(addr))

#define MMA_BF16(c, a0, a1, a2, a3, b0, b1)                                 \
    asm volatile("mma.sync.aligned.m16n8k16.row.col.f32.bf16.bf16.f32 "     \
        "{%0,%1,%2,%3}, {%4,%5,%6,%7}, {%8,%9}, {%0,%1,%2,%3};"             \
        : "+f"((c)[0]), "+f"((c)[1]), "+f"((c)[2]), "+f"((c)[3])            \
        : "r"(a0), "r"(a1), "r"(a2), "r"(a3), "r"(b0), "r"(b1))

// SMEM layout (dynamic, byte offsets)
#define OFF_SW_HI 0        // Wi2 hi  [r][k] 64x128B  (8 KB)
#define OFF_SW_LO 8192     // Wi2 lo                  (8 KB)
#define OFF_SX_HI 16384    // x1 hi   [j][k] 128x128B (16 KB)
#define OFF_SX_LO 32768    // x1 lo                   (16 KB)
#define OFF_SS    49152    // s_j (128 floats)
#define OFF_WRED  49664    // colacc partials [2][64]
#define OFF_QRED  50176    // quantum partials [8][32]
#define OFF_SRED  51200    // ssum partials [8]
#define SMEM_TOT  51712

__device__ __forceinline__ uint32_t sw128(uint32_t off) {
    return off ^ ((off >> 3) & 0x70);
}

// ---------------------------------------------------------------------------
// Phase 1: per-node precompute (unchanged)
// ---------------------------------------------------------------------------
__global__ void phase1_kernel(
    const float* __restrict__ state,
    const float* __restrict__ Ws1, const float* __restrict__ bs1,
    const float* __restrict__ Ws2, const float* __restrict__ bs2,
    const float* __restrict__ Ws3, const float* __restrict__ bs3,
    const float* __restrict__ Wi1, const float* __restrict__ bi1,
    const float* __restrict__ Wc,  const float* __restrict__ aggr)
{
    int i = blockIdx.x;
    int t = threadIdx.x;
    __shared__ float sh[LD], st1[HD], st2[HD], sdh[LD];

    if (t < LD) sh[t] = state[i * (LD + 1) + t];
    __syncthreads();

    float acc = bs1[t];
#pragma unroll
    for (int l = 0; l < LD; l++) acc += Ws1[t * LD + l] * sh[l];
    st1[t] = tanhf(acc);
    __syncthreads();

    acc = bs2[t];
#pragma unroll
    for (int k = 0; k < HD; k++) acc += Ws2[t * HD + k] * st1[k];
    st2[t] = tanhf(acc);
    __syncthreads();

    if (t < LD) {
        acc = bs3[t];
#pragma unroll
        for (int k = 0; k < HD; k++) acc += Ws3[t * HD + k] * st2[k];
        sdh[t] = acc;
        g_SELF[i * LD + t] = acc;
        g_Hh[i * LD + t] = sh[t];
    }
    __syncthreads();

    float a = 0.0f, b = bi1[t];
#pragma unroll
    for (int l = 0; l < LD; l++) {
        float hv = sh[l], dv = sdh[l];
        const float* row = Wi1 + t * (4 * LD);
        a += row[l] * hv + row[2 * LD + l] * dv;
        b += row[LD + l] * hv + row[3 * LD + l] * dv;
    }
    g_A[i * HD + t] = a;
    g_Bv[i * HD + t] = b;

    if (t < LD) {
        float ci = 0.0f, cj = 0.0f;
#pragma unroll
        for (int m = 0; m < LD; m++) {
            ci += Wc[t * (2 * LD) + m] * sh[m];
            cj += Wc[t * (2 * LD) + LD + m] * sh[m];
        }
        g_CI[i * LD + t] = ci;
        g_CJ[i * LD + t] = cj;
    }
    if (t == 0) {
        g_AG[i] = 1.0f / (1.0f + expf(-aggr[i]));
        g_PH[i] = state[i * (LD + 1) + LD];
    }
}

// ---------------------------------------------------------------------------
// Phase 2: HMMA split-bf16. One block (256 thr) per i; j tiled by 128.
// Warp w = (jh = w&1, rq = w>>1): output patch 64j x 16r, D in registers.
// ---------------------------------------------------------------------------
__global__ void __launch_bounds__(NT, 2) phase2_kernel(
    const float* __restrict__ Wi2, const float* __restrict__ bi2,
    const float* __restrict__ Wi3, const float* __restrict__ bi3,
    const float* __restrict__ phase_w, const float* __restrict__ bc,
    float* __restrict__ out)
{
    extern __shared__ char smem[];
    const uint32_t smem_base = smem_u32(smem);
    const int i = blockIdx.x;
    const int tid = threadIdx.x;
    const int lane = tid & 31;
    const int warp = tid >> 5;

    float* sSp   = (float*)(smem + OFF_SS);
    float* sWRed = (float*)(smem + OFF_WRED);
    float* sQRed = (float*)(smem + OFF_QRED);
    float* sSRed = (float*)(smem + OFF_SRED);

    // ---- load Wi2 hi/lo into swizzled SMEM [r][k] (ldmatrix-B layout) ----
    for (int idx = tid; idx < HD * 32; idx += NT) {   // 64 rows x 32 words
        int r = idx >> 5, w = idx & 31;
        float2 v = *(const float2*)(Wi2 + r * HD + 2 * w);
        __nv_bfloat16 h0 = __float2bfloat16(v.x), h1 = __float2bfloat16(v.y);
        __nv_bfloat16 l0 = __float2bfloat16(v.x - __bfloat162float(h0));
        __nv_bfloat16 l1 = __float2bfloat16(v.y - __bfloat162float(h1));
        uint32_t hw = ((uint32_t)__bfloat16_as_ushort(h1) << 16) | __bfloat16_as_ushort(h0);
        uint32_t lw = ((uint32_t)__bfloat16_as_ushort(l1) << 16) | __bfloat16_as_ushort(l0);
        uint32_t sw = sw128(r * 128 + w * 4);
        *(uint32_t*)(smem + OFF_SW_HI + sw) = hw;
        *(uint32_t*)(smem + OFF_SW_LO + sw) = lw;
    }

    // ---- per-lane constants ----
    const float agg_i = g_AG[i];
    const float ph_i  = g_PH[i];
    const float hi_l  = g_Hh[i * LD + lane];
    const float ci_l  = g_CI[i * LD + lane];
    const float pw_l  = phase_w[lane];
    const float bc_l  = bc[lane];
    const float ak0   = g_A[i * HD + 2 * lane];
    const float ak1   = g_A[i * HD + 2 * lane + 1];

    // MMA tiling constants
    const int jb = (warp & 1) * 64;
    const int rb = (warp >> 1) * 16;

    uint32_t rowAoff[4], swA[4];
#pragma unroll
    for (int mt = 0; mt < 4; mt++) {
        uint32_t ro = (uint32_t)(jb + mt * 16 + (lane & 15)) * 128;
        rowAoff[mt] = ro;
        swA[mt] = (ro >> 3) & 0x70;
    }
    const uint32_t kaddA = (uint32_t)(lane & 16);          // +16B if lane>=16
    const uint32_t rowBoff = (uint32_t)(rb + (lane & 7) + ((lane & 16) >> 1)) * 128;
    const uint32_t swB = (rowBoff >> 3) & 0x70;
    const uint32_t kaddB = (uint32_t)((lane & 8) << 1);    // +16B if lane bit3

    // bi2 values for this lane's 4 r-columns
    float bi2v[4];
#pragma unroll
    for (int nt = 0; nt < 2; nt++)
#pragma unroll
        for (int cb = 0; cb < 2; cb++)
            bi2v[nt * 2 + cb] = bi2[rb + nt * 8 + (lane & 3) * 2 + cb];

    float colacc[4] = {0.f, 0.f, 0.f, 0.f};
    float qacc = 0.f, ssum = 0.f;

    // =================== main loop over 8 j-tiles ===================
    for (int t = 0; t < 8; t++) {
        const int j0 = t * 128;

        // ---- stage A1: produce x1 hi/lo for 16 j owned by this warp ----
#pragma unroll 2
        for (int v = 0; v < 16; v++) {
            int jl = warp * 16 + v;                 // tile-local j
            float2 b2 = *(const float2*)(g_Bv + (j0 + jl) * HD + 2 * lane);
            float x0 = tanh_fast(ak0 + b2.x);
            float x1v = tanh_fast(ak1 + b2.y);
            __nv_bfloat16 h0 = __float2bfloat16(x0), h1 = __float2bfloat16(x1v);
            __nv_bfloat16 l0 = __float2bfloat16(x0 - __bfloat162float(h0));
            __nv_bfloat16 l1 = __float2bfloat16(x1v - __bfloat162float(h1));
            uint32_t hw = ((uint32_t)__bfloat16_as_ushort(h1) << 16) | __bfloat16_as_ushort(h0);
            uint32_t lw = ((uint32_t)__bfloat16_as_ushort(l1) << 16) | __bfloat16_as_ushort(l0);
            uint32_t sw = sw128((uint32_t)jl * 128 + lane * 4);
            *(uint32_t*)(smem + OFF_SX_HI + sw) = hw;
            *(uint32_t*)(smem + OFF_SX_LO + sw) = lw;
        }

        // ---- stage A2: s_j + quantum for the same 16 j (lane = l) ----
#pragma unroll 1
        for (int v = 0; v < 16; v++) {
            int j = j0 + warp * 16 + v;
            float hj = g_Hh[j * LD + lane];
            float e = hj - hi_l;
            float d2 = e * e;
#pragma unroll
            for (int o = 16; o > 0; o >>= 1) d2 += __shfl_xor_sync(0xffffffffu, d2, o);
            float s = fminf(__fdividef(1.0f, sqrtf(d2) + EPSV), 2.0f) * agg_i;
            if (j == i) s = 0.0f;
            float pd = ph_i - g_PH[j];
            float pf = __cosf(pd * pw_l);
            float z = ci_l + g_CJ[j * LD + lane] + bc_l;
            float coh = __fdividef(1.0f, 1.0f + __expf(-z));
            qacc += pf * coh * e;
            if (lane == 0) { sSp[warp * 16 + v] = s; ssum += s; }
        }
        __syncthreads();   // x1 tiles + sS visible

        // ---- stage B: 3-pass split-bf16 MMA, D in registers ----
        float acc[4][2][4];
#pragma unroll
        for (int mt = 0; mt < 4; mt++)
#pragma unroll
            for (int nt = 0; nt < 2; nt++)
#pragma unroll
                for (int c = 0; c < 4; c++) acc[mt][nt][c] = 0.0f;

#pragma unroll
        for (int pass = 0; pass < 3; pass++) {
            const uint32_t aB = smem_base + (pass == 1 ? OFF_SX_LO : OFF_SX_HI);
            const uint32_t bB = smem_base + (pass == 2 ? OFF_SW_LO : OFF_SW_HI);
#pragma unroll
            for (int ks = 0; ks < 4; ks++) {
                const uint32_t kb = ks * 32;
                uint32_t b0, b1, b2r, b3;
                LDM4(b0, b1, b2r, b3, bB + rowBoff + ((kb + kaddB) ^ swB));
#pragma unroll
                for (int mt = 0; mt < 4; mt++) {
                    uint32_t a0, a1, a2, a3;
                    LDM4(a0, a1, a2, a3, aB + rowAoff[mt] + ((kb + kaddA) ^ swA[mt]));
                    MMA_BF16(acc[mt][0], a0, a1, a2, a3, b0, b1);
                    MMA_BF16(acc[mt][1], a0, a1, a2, a3, b2r, b3);
                }
            }
        }

        // ---- epilogue: tanh, weight by s_j, fold into colacc ----
#pragma unroll
        for (int mt = 0; mt < 4; mt++) {
            float s_a = sSp[jb + mt * 16 + (lane >> 2)];
            float s_b = sSp[jb + mt * 16 + 8 + (lane >> 2)];
#pragma unroll
            for (int nt = 0; nt < 2; nt++) {
#pragma unroll
                for (int c = 0; c < 4; c++) {
                    float x2 = tanh_fast(acc[mt][nt][c] + bi2v[nt * 2 + (c & 1)]);
                    colacc[nt * 2 + (c & 1)] += (c < 2 ? s_a : s_b) * x2;
                }
            }
        }
        __syncthreads();   // done reading sX/sS before next tile overwrites
    }

    // =================== final reductions ===================
#pragma unroll
    for (int q = 0; q < 4; q++) {
        float v = colacc[q];
        v += __shfl_xor_sync(0xffffffffu, v, 4);
        v += __shfl_xor_sync(0xffffffffu, v, 8);
        v += __shfl_xor_sync(0xffffffffu, v, 16);
        colacc[q] = v;
    }
    if (lane < 4) {
#pragma unroll
        for (int nt = 0; nt < 2; nt++)
#pragma unroll
            for (int cb = 0; cb < 2; cb++)
                sWRed[(warp & 1) * 64 + rb + nt * 8 + lane * 2 + cb] = colacc[nt * 2 + cb];
    }
    sQRed[warp * 32 + lane] = qacc;
    if (lane == 0) sSRed[warp] = ssum;
    __syncthreads();

    if (tid < LD) {
        float q = 0.0f;
#pragma unroll
        for (int w = 0; w < 8; w++) q += sQRed[w * 32 + tid];
        float sst = 0.0f;
#pragma unroll
        for (int w = 0; w < 8; w++) sst += sSRed[w];
        float kv = sst * bi3[tid];
#pragma unroll
        for (int r = 0; r < HD; r++)
            kv += (sWRed[r] + sWRed[64 + r]) * Wi3[tid * HD + r];
        float v = kv + q;
        out[i * (LD + 1) + tid] = SELF_SCALE * g_SELF[i * LD + tid] + INT_SCALE * v;
        float av = fabsf(v);
#pragma unroll
        for (int o = 16; o > 0; o >>= 1)
            av += __shfl_down_sync(0xffffffffu, av, o);
        if (tid == 0)
            out[i * (LD + 1) + LD] = 0.1f + 0.05f * av;
    }
}

// ---------------------------------------------------------------------------
extern "C" void kernel_launch(void* const* d_in, const int* in_sizes, int n_in,
                              void* d_out, int out_size)
{
    const float* state   = (const float*)d_in[0];
    const float* Ws1     = (const float*)d_in[1];
    const float* bs1     = (const float*)d_in[2];
    const float* Ws2     = (const float*)d_in[3];
    const float* bs2     = (const float*)d_in[4];
    const float* Ws3     = (const float*)d_in[5];
    const float* bs3     = (const float*)d_in[6];
    const float* Wi1     = (const float*)d_in[7];
    const float* bi1     = (const float*)d_in[8];
    const float* Wi2     = (const float*)d_in[9];
    const float* bi2     = (const float*)d_in[10];
    const float* Wi3     = (const float*)d_in[11];
    const float* bi3     = (const float*)d_in[12];
    const float* phase_w = (const float*)d_in[13];
    const float* Wc      = (const float*)d_in[14];
    const float* bc      = (const float*)d_in[15];
    const float* aggr    = (const float*)d_in[16];
    float* out = (float*)d_out;

    cudaFuncSetAttribute(phase2_kernel,
                         cudaFuncAttributeMaxDynamicSharedMemorySize, SMEM_TOT);

    phase1_kernel<<<NB, 64>>>(state, Ws1, bs1, Ws2, bs2, Ws3, bs3,
                              Wi1, bi1, Wc, aggr);
    phase2_kernel<<<NB, NT, SMEM_TOT>>>(Wi2, bi2, Wi3, bi3, phase_w, bc, out);
}

// round 12
// speedup vs baseline: 1.9748x; 1.4836x over previous
#include <cuda_runtime.h>
#include <cuda_bf16.h>
#include <cstdint>

#define NB 1024
#define LD 32
#define HD 64
#define NT 256
#define EPSV 1e-6f
#define SELF_SCALE 0.5f
#define INT_SCALE 0.3f

// ---------------- device scratch ----------------
__device__ __align__(16) float g_A[NB * HD];     // a_i   [i][k]
__device__ __align__(16) float g_Bv[NB * HD];    // b_j   [j][k]
__device__ __align__(16) float g_CI[NB * LD];
__device__ __align__(16) float g_CJ[NB * LD];
__device__ __align__(16) float g_SELF[NB * LD];
__device__ __align__(16) float g_Hh[NB * LD];
__device__ __align__(16) float g_CS[NB * LD];    // cos(ph_j * pw_l)
__device__ __align__(16) float g_SN[NB * LD];    // sin(ph_j * pw_l)
__device__ __align__(16) float g_S[NB * NB];     // s_ij (4 MB)
__device__ __align__(16) float g_Q[NB * LD];     // quantum sum per (i,l)
__device__ float g_SS[NB];                       // sum_j s_ij
__device__ float g_AG[NB];

__device__ __forceinline__ float tanh_fast(float x) {
    float e = __expf(2.0f * x);
    return 1.0f - __fdividef(2.0f, e + 1.0f);
}

__device__ __forceinline__ uint32_t smem_u32(const void* p) {
    uint32_t a;
    asm("{ .reg .u64 t; cvta.to.shared.u64 t, %1; cvt.u32.u64 %0, t; }" : "=r"(a) : "l"(p));
    return a;
}

#define LDM4(r0, r1, r2, r3, addr)                                          \
    asm volatile("ldmatrix.sync.aligned.m8n8.x4.shared.b16 {%0,%1,%2,%3}, [%4];" \
        : "=r"(r0), "=r"(r1), "=r"(r2), "=r"(r3) : "r"(addr))

#define MMA_BF16(c, a0, a1, a2, a3, b0, b1)                                 \
    asm volatile("mma.sync.aligned.m16n8k16.row.col.f32.bf16.bf16.f32 "     \
        "{%0,%1,%2,%3}, {%4,%5,%6,%7}, {%8,%9}, {%0,%1,%2,%3};"             \
        : "+f"((c)[0]), "+f"((c)[1]), "+f"((c)[2]), "+f"((c)[3])            \
        : "r"(a0), "r"(a1), "r"(a2), "r"(a3), "r"(b0), "r"(b1))

// SMEM layout (dynamic, byte offsets)
#define OFF_SW_HI 0        // Wi2 hi  [r][k] 64x128B  (8 KB)
#define OFF_SW_LO 8192     // Wi2 lo                  (8 KB)
#define OFF_SX_HI 16384    // x1 hi   [j][k] 128x128B (16 KB)
#define OFF_SX_LO 32768    // x1 lo                   (16 KB)
#define OFF_SS    49152    // s_j (128 floats)
#define OFF_WRED  49664    // colacc partials [2][64]
#define SMEM_TOT  50176

__device__ __forceinline__ uint32_t sw128(uint32_t off) {
    return off ^ ((off >> 3) & 0x70);
}

// ---------------------------------------------------------------------------
// Phase 1: per-node precompute (+ cos/sin tables)
// ---------------------------------------------------------------------------
__global__ void phase1_kernel(
    const float* __restrict__ state,
    const float* __restrict__ Ws1, const float* __restrict__ bs1,
    const float* __restrict__ Ws2, const float* __restrict__ bs2,
    const float* __restrict__ Ws3, const float* __restrict__ bs3,
    const float* __restrict__ Wi1, const float* __restrict__ bi1,
    const float* __restrict__ Wc,  const float* __restrict__ aggr,
    const float* __restrict__ phase_w)
{
    int i = blockIdx.x;
    int t = threadIdx.x;
    __shared__ float sh[LD], st1[HD], st2[HD], sdh[LD];

    if (t < LD) sh[t] = state[i * (LD + 1) + t];
    __syncthreads();

    float acc = bs1[t];
#pragma unroll
    for (int l = 0; l < LD; l++) acc += Ws1[t * LD + l] * sh[l];
    st1[t] = tanhf(acc);
    __syncthreads();

    acc = bs2[t];
#pragma unroll
    for (int k = 0; k < HD; k++) acc += Ws2[t * HD + k] * st1[k];
    st2[t] = tanhf(acc);
    __syncthreads();

    if (t < LD) {
        acc = bs3[t];
#pragma unroll
        for (int k = 0; k < HD; k++) acc += Ws3[t * HD + k] * st2[k];
        sdh[t] = acc;
        g_SELF[i * LD + t] = acc;
        g_Hh[i * LD + t] = sh[t];
    }
    __syncthreads();

    float a = 0.0f, b = bi1[t];
#pragma unroll
    for (int l = 0; l < LD; l++) {
        float hv = sh[l], dv = sdh[l];
        const float* row = Wi1 + t * (4 * LD);
        a += row[l] * hv + row[2 * LD + l] * dv;
        b += row[LD + l] * hv + row[3 * LD + l] * dv;
    }
    g_A[i * HD + t] = a;
    g_Bv[i * HD + t] = b;

    if (t < LD) {
        float ci = 0.0f, cj = 0.0f;
#pragma unroll
        for (int m = 0; m < LD; m++) {
            ci += Wc[t * (2 * LD) + m] * sh[m];
            cj += Wc[t * (2 * LD) + LD + m] * sh[m];
        }
        g_CI[i * LD + t] = ci;
        g_CJ[i * LD + t] = cj;

        float ph = state[i * (LD + 1) + LD];
        float cs, sn;
        sincosf(ph * phase_w[t], &sn, &cs);
        g_CS[i * LD + t] = cs;
        g_SN[i * LD + t] = sn;
    }
    if (t == 0)
        g_AG[i] = 1.0f / (1.0f + expf(-aggr[i]));
}

// ---------------------------------------------------------------------------
// Phase 1.5: pairwise s_ij + quantum sums. Block per i, warp per 128 j.
// ---------------------------------------------------------------------------
__global__ void __launch_bounds__(NT) p15_kernel(const float* __restrict__ bc)
{
    __shared__ float sQ[8][LD];
    __shared__ float sSr[8];

    const int i = blockIdx.x;
    const int tid = threadIdx.x;
    const int lane = tid & 31;
    const int warp = tid >> 5;

    const float agg_i = g_AG[i];
    const float hi_l  = g_Hh[i * LD + lane];
    const float ci_l  = g_CI[i * LD + lane];
    const float bc_l  = bc[lane];
    const float cs_i  = g_CS[i * LD + lane];
    const float sn_i  = g_SN[i * LD + lane];

    float qacc = 0.0f, ssum = 0.0f;

#pragma unroll 2
    for (int v = 0; v < 128; v++) {
        int j = warp * 128 + v;
        float hj = g_Hh[j * LD + lane];
        float e = hj - hi_l;
        float d2 = e * e;
#pragma unroll
        for (int o = 16; o > 0; o >>= 1)
            d2 += __shfl_xor_sync(0xffffffffu, d2, o);
        float s = fminf(rsqrtf(d2), 2.0f) * agg_i;   // == min(1/(sqrt+eps),2) to 2e-6
        if (j == i) s = 0.0f;

        float pf = cs_i * g_CS[j * LD + lane] + sn_i * g_SN[j * LD + lane];
        float z  = ci_l + g_CJ[j * LD + lane] + bc_l;
        float coh = __fdividef(1.0f, 1.0f + __expf(-z));
        qacc += pf * coh * e;

        if (lane == 0) { g_S[i * NB + j] = s; ssum += s; }
    }

    sQ[warp][lane] = qacc;
    if (lane == 0) sSr[warp] = ssum;
    __syncthreads();

    if (tid < LD) {
        float q = 0.0f;
#pragma unroll
        for (int w = 0; w < 8; w++) q += sQ[w][tid];
        g_Q[i * LD + tid] = q;
    }
    if (tid == 0) {
        float sst = 0.0f;
#pragma unroll
        for (int w = 0; w < 8; w++) sst += sSr[w];
        g_SS[i] = sst;
    }
}

// ---------------------------------------------------------------------------
// Phase 2: HMMA split-bf16 pipeline (pure GEMM now). One block per i.
// ---------------------------------------------------------------------------
__global__ void __launch_bounds__(NT, 2) phase2_kernel(
    const float* __restrict__ Wi2, const float* __restrict__ bi2,
    const float* __restrict__ Wi3, const float* __restrict__ bi3,
    float* __restrict__ out)
{
    extern __shared__ char smem[];
    const uint32_t smem_base = smem_u32(smem);
    const int i = blockIdx.x;
    const int tid = threadIdx.x;
    const int lane = tid & 31;
    const int warp = tid >> 5;

    float* sSp   = (float*)(smem + OFF_SS);
    float* sWRed = (float*)(smem + OFF_WRED);

    // ---- Wi2 hi/lo into swizzled SMEM [r][k] ----
    for (int idx = tid; idx < HD * 32; idx += NT) {
        int r = idx >> 5, w = idx & 31;
        float2 v = *(const float2*)(Wi2 + r * HD + 2 * w);
        __nv_bfloat16 h0 = __float2bfloat16(v.x), h1 = __float2bfloat16(v.y);
        __nv_bfloat16 l0 = __float2bfloat16(v.x - __bfloat162float(h0));
        __nv_bfloat16 l1 = __float2bfloat16(v.y - __bfloat162float(h1));
        uint32_t hw = ((uint32_t)__bfloat16_as_ushort(h1) << 16) | __bfloat16_as_ushort(h0);
        uint32_t lw = ((uint32_t)__bfloat16_as_ushort(l1) << 16) | __bfloat16_as_ushort(l0);
        uint32_t sw = sw128(r * 128 + w * 4);
        *(uint32_t*)(smem + OFF_SW_HI + sw) = hw;
        *(uint32_t*)(smem + OFF_SW_LO + sw) = lw;
    }

    const float ak0 = g_A[i * HD + 2 * lane];
    const float ak1 = g_A[i * HD + 2 * lane + 1];

    const int jb = (warp & 1) * 64;
    const int rb = (warp >> 1) * 16;

    uint32_t rowAoff[4], swA[4];
#pragma unroll
    for (int mt = 0; mt < 4; mt++) {
        uint32_t ro = (uint32_t)(jb + mt * 16 + (lane & 15)) * 128;
        rowAoff[mt] = ro;
        swA[mt] = (ro >> 3) & 0x70;
    }
    const uint32_t kaddA = (uint32_t)(lane & 16);
    const uint32_t rowBoff = (uint32_t)(rb + (lane & 7) + ((lane & 16) >> 1)) * 128;
    const uint32_t swB = (rowBoff >> 3) & 0x70;
    const uint32_t kaddB = (uint32_t)((lane & 8) << 1);

    float bi2v[4];
#pragma unroll
    for (int nt = 0; nt < 2; nt++)
#pragma unroll
        for (int cb = 0; cb < 2; cb++)
            bi2v[nt * 2 + cb] = bi2[rb + nt * 8 + (lane & 3) * 2 + cb];

    float colacc[4] = {0.f, 0.f, 0.f, 0.f};

    // =================== main loop over 8 j-tiles ===================
    for (int t = 0; t < 8; t++) {
        const int j0 = t * 128;

        // ---- produce x1 hi/lo for 16 j owned by this warp ----
#pragma unroll 2
        for (int v = 0; v < 16; v++) {
            int jl = warp * 16 + v;
            float2 b2 = *(const float2*)(g_Bv + (j0 + jl) * HD + 2 * lane);
            float x0 = tanh_fast(ak0 + b2.x);
            float x1v = tanh_fast(ak1 + b2.y);
            __nv_bfloat16 h0 = __float2bfloat16(x0), h1 = __float2bfloat16(x1v);
            __nv_bfloat16 l0 = __float2bfloat16(x0 - __bfloat162float(h0));
            __nv_bfloat16 l1 = __float2bfloat16(x1v - __bfloat162float(h1));
            uint32_t hw = ((uint32_t)__bfloat16_as_ushort(h1) << 16) | __bfloat16_as_ushort(h0);
            uint32_t lw = ((uint32_t)__bfloat16_as_ushort(l1) << 16) | __bfloat16_as_ushort(l0);
            uint32_t sw = sw128((uint32_t)jl * 128 + lane * 4);
            *(uint32_t*)(smem + OFF_SX_HI + sw) = hw;
            *(uint32_t*)(smem + OFF_SX_LO + sw) = lw;
        }
        if (tid < 128) sSp[tid] = g_S[i * NB + j0 + tid];
        __syncthreads();

        // ---- 3-pass split-bf16 MMA, D in registers ----
        float acc[4][2][4];
#pragma unroll
        for (int mt = 0; mt < 4; mt++)
#pragma unroll
            for (int nt = 0; nt < 2; nt++)
#pragma unroll
                for (int c = 0; c < 4; c++) acc[mt][nt][c] = 0.0f;

#pragma unroll
        for (int pass = 0; pass < 3; pass++) {
            const uint32_t aB = smem_base + (pass == 1 ? OFF_SX_LO : OFF_SX_HI);
            const uint32_t bB = smem_base + (pass == 2 ? OFF_SW_LO : OFF_SW_HI);
#pragma unroll
            for (int ks = 0; ks < 4; ks++) {
                const uint32_t kb = ks * 32;
                uint32_t b0, b1, b2r, b3;
                LDM4(b0, b1, b2r, b3, bB + rowBoff + ((kb + kaddB) ^ swB));
#pragma unroll
                for (int mt = 0; mt < 4; mt++) {
                    uint32_t a0, a1, a2, a3;
                    LDM4(a0, a1, a2, a3, aB + rowAoff[mt] + ((kb + kaddA) ^ swA[mt]));
                    MMA_BF16(acc[mt][0], a0, a1, a2, a3, b0, b1);
                    MMA_BF16(acc[mt][1], a0, a1, a2, a3, b2r, b3);
                }
            }
        }

        // ---- epilogue: tanh, weight by s_j, fold into colacc ----
#pragma unroll
        for (int mt = 0; mt < 4; mt++) {
            float s_a = sSp[jb + mt * 16 + (lane >> 2)];
            float s_b = sSp[jb + mt * 16 + 8 + (lane >> 2)];
#pragma unroll
            for (int nt = 0; nt < 2; nt++) {
#pragma unroll
                for (int c = 0; c < 4; c++) {
                    float x2 = tanh_fast(acc[mt][nt][c] + bi2v[nt * 2 + (c & 1)]);
                    colacc[nt * 2 + (c & 1)] += (c < 2 ? s_a : s_b) * x2;
                }
            }
        }
        __syncthreads();
    }

    // =================== final reductions ===================
#pragma unroll
    for (int q = 0; q < 4; q++) {
        float v = colacc[q];
        v += __shfl_xor_sync(0xffffffffu, v, 4);
        v += __shfl_xor_sync(0xffffffffu, v, 8);
        v += __shfl_xor_sync(0xffffffffu, v, 16);
        colacc[q] = v;
    }
    if (lane < 4) {
#pragma unroll
        for (int nt = 0; nt < 2; nt++)
#pragma unroll
            for (int cb = 0; cb < 2; cb++)
                sWRed[(warp & 1) * 64 + rb + nt * 8 + lane * 2 + cb] = colacc[nt * 2 + cb];
    }
    __syncthreads();

    if (tid < LD) {
        float q = g_Q[i * LD + tid];
        float sst = g_SS[i];
        float kv = sst * bi3[tid];
#pragma unroll
        for (int r = 0; r < HD; r++)
            kv += (sWRed[r] + sWRed[64 + r]) * Wi3[tid * HD + r];
        float v = kv + q;
        out[i * (LD + 1) + tid] = SELF_SCALE * g_SELF[i * LD + tid] + INT_SCALE * v;
        float av = fabsf(v);
#pragma unroll
        for (int o = 16; o > 0; o >>= 1)
            av += __shfl_down_sync(0xffffffffu, av, o);
        if (tid == 0)
            out[i * (LD + 1) + LD] = 0.1f + 0.05f * av;
    }
}

// ---------------------------------------------------------------------------
extern "C" void kernel_launch(void* const* d_in, const int* in_sizes, int n_in,
                              void* d_out, int out_size)
{
    const float* state   = (const float*)d_in[0];
    const float* Ws1     = (const float*)d_in[1];
    const float* bs1     = (const float*)d_in[2];
    const float* Ws2     = (const float*)d_in[3];
    const float* bs2     = (const float*)d_in[4];
    const float* Ws3     = (const float*)d_in[5];
    const float* bs3     = (const float*)d_in[6];
    const float* Wi1     = (const float*)d_in[7];
    const float* bi1     = (const float*)d_in[8];
    const float* Wi2     = (const float*)d_in[9];
    const float* bi2     = (const float*)d_in[10];
    const float* Wi3     = (const float*)d_in[11];
    const float* bi3     = (const float*)d_in[12];
    const float* phase_w = (const float*)d_in[13];
    const float* Wc      = (const float*)d_in[14];
    const float* bc      = (const float*)d_in[15];
    const float* aggr    = (const float*)d_in[16];
    float* out = (float*)d_out;

    cudaFuncSetAttribute(phase2_kernel,
                         cudaFuncAttributeMaxDynamicSharedMemorySize, SMEM_TOT);

    phase1_kernel<<<NB, 64>>>(state, Ws1, bs1, Ws2, bs2, Ws3, bs3,
                              Wi1, bi1, Wc, aggr, phase_w);
    p15_kernel<<<NB, NT>>>(bc);
    phase2_kernel<<<NB, NT, SMEM_TOT>>>(Wi2, bi2, Wi3, bi3, out);
}